// round 5
// baseline (speedup 1.0000x reference)
#include <cuda_runtime.h>

#define NB     16
#define NP     65536
#define RAD_N  5
#define AZI_N  30
#define ELE_N  15
#define KSL    (ELE_N - 1)                         // 14 ele pair-slots
#define NSLOT  (NB * RAD_N * AZI_N * KSL)          // 33600 float4 2x2-slots
#define NOUT   (NB * RAD_N * AZI_N * ELE_N)        // 36000 output bins

#define NBLK   256
#define NTHR   256
#define NT     (NBLK * NTHR)                       // 65536 threads

// 2x2 pair-slot histogram: slot[b][r][a][k] (a circular, k=0..13) holds
// contributions to bins (a,k),(a,k+1),(a+1%30,k),(a+1%30,k+1) in (.x,.y,.z,.w).
__device__ float4 g_slots[NSLOT];

// Software grid barrier state. g_bar_gen is monotone across graph replays
// (no reset needed); g_bar_count self-resets each barrier.
__device__ unsigned g_bar_count = 0;
__device__ unsigned g_bar_gen   = 0;

__device__ __forceinline__ void grid_barrier() {
    __threadfence();          // order phase memory ops (STG / red.global) before release
    __syncthreads();
    if (threadIdx.x == 0) {
        unsigned old = atomicAdd(&g_bar_gen, 0u);
        unsigned t   = atomicAdd(&g_bar_count, 1u);
        if (t == NBLK - 1) {
            atomicExch(&g_bar_count, 0u);
            __threadfence();
            atomicAdd(&g_bar_gen, 1u);
        } else {
            while (atomicAdd(&g_bar_gen, 0u) == old) { __nanosleep(64); }
        }
    }
    __syncthreads();
}

__device__ __forceinline__ void red_add4(float4* a, float x, float y, float z, float w) {
    asm volatile("red.global.add.v4.f32 [%0], {%1, %2, %3, %4};"
                 :: "l"(a), "f"(x), "f"(y), "f"(z), "f"(w) : "memory");
}

__global__ void __launch_bounds__(NTHR, 2) fused_kernel(const float* __restrict__ pts,
                                                        float* __restrict__ out) {
    int gtid = blockIdx.x * NTHR + threadIdx.x;

    // ---- Phase 0: zero the pair-slot table ----
    if (gtid < NSLOT) g_slots[gtid] = make_float4(0.f, 0.f, 0.f, 0.f);

    grid_barrier();

    // ---- Phase 1: scatter (16 points per thread, coalesced stride) ----
    #pragma unroll 1
    for (int idx = gtid; idx < NB * NP; idx += NT) {
        float x = __ldg(pts + 3 * idx);
        float y = __ldg(pts + 3 * idx + 1);
        float z = __ldg(pts + 3 * idx + 2);

        float r = sqrtf(x * x + y * y + z * z);
        if (r > 2.0f) continue;   // reference culls r > DES_R (all weights zero)

        int b = idx >> 16;        // NP = 65536

        float azi = atan2f(y, x);
        if (azi < 0.f) azi += 6.28318530717958647692f;
        float ce  = fminf(fmaxf(z / fmaxf(r, 1e-12f), -1.f), 1.f);
        float ele = acosf(ce);

        // radial pair: tr=0.4, closed form of ref's half-bin boundary clamps
        float vr = r * 2.5f - 0.5f;
        int jr; float wr0, wr1;
        if (vr < 0.f)        { jr = 0; wr0 = 1.f; wr1 = 0.f; }
        else if (vr >= 4.f)  { jr = 3; wr0 = 0.f; wr1 = 5.f - vr; }
        else { jr = (int)vr; float f = vr - (float)jr; wr0 = 1.f - f; wr1 = f; }

        // azimuth pair: circular; slot sa covers bins (sa, sa+1 mod 30)
        float va = azi * (float)(AZI_N / 6.283185307179586) - 0.5f;
        float fj = floorf(va);
        int   j  = (int)fj;                 // in [-1, 29]
        float fa = va - fj;
        int sa = (j < 0) ? (AZI_N - 1) : j;
        float wa0 = 1.f - fa, wa1 = fa;

        // elevation pair: te = pi/15, both-end half-bin clamps
        float ve = ele * (float)(ELE_N / 3.141592653589793) - 0.5f;
        int ke; float we0, we1;
        if (ve < 0.f)         { ke = 0;  we0 = 1.f; we1 = 0.f; }
        else if (ve >= 14.f)  { ke = 13; we0 = 0.f; we1 = 1.f; }
        else { ke = (int)ve; float f = ve - (float)ke; we0 = 1.f - f; we1 = f; }

        float p00 = wa0 * we0, p01 = wa0 * we1;
        float p10 = wa1 * we0, p11 = wa1 * we1;

        int s0 = ((b * RAD_N + jr) * AZI_N + sa) * KSL + ke;
        if (wr0 != 0.f)
            red_add4(&g_slots[s0], wr0 * p00, wr0 * p01, wr0 * p10, wr0 * p11);
        if (wr1 != 0.f)
            red_add4(&g_slots[s0 + AZI_N * KSL], wr1 * p00, wr1 * p01, wr1 * p10, wr1 * p11);
    }

    grid_barrier();

    // ---- Phase 2: fold pair-slots into output bins ----
    // MUST bypass L1 (__ldcg): red.global updates L2 only; L1 may hold stale
    // zero lines from phase 0.
    if (gtid < NOUT) {
        int e   = gtid % ELE_N;
        int ra  = gtid / ELE_N;       // (b*5 + r)*30 + a
        int a   = ra % AZI_N;
        int rb  = ra / AZI_N;         // b*5 + r
        int am1 = (a == 0) ? (AZI_N - 1) : (a - 1);

        const float4* S = g_slots + rb * AZI_N * KSL;
        float v = 0.f;
        if (e < KSL) {
            float4 s0 = __ldcg(&S[a   * KSL + e]);
            float4 s1 = __ldcg(&S[am1 * KSL + e]);
            v += s0.x + s1.z;
        }
        if (e > 0) {
            float4 s0 = __ldcg(&S[a   * KSL + e - 1]);
            float4 s1 = __ldcg(&S[am1 * KSL + e - 1]);
            v += s0.y + s1.w;
        }
        out[gtid] = v;
    }
}

extern "C" void kernel_launch(void* const* d_in, const int* in_sizes, int n_in,
                              void* d_out, int out_size) {
    const float* pts = (const float*)d_in[0];
    float* out = (float*)d_out;
    fused_kernel<<<NBLK, NTHR>>>(pts, out);
}

// round 7
// speedup vs baseline: 1.2145x; 1.2145x over previous
#include <cuda_runtime.h>

#define NB     16
#define NP     65536
#define RAD_N  5
#define AZI_N  30
#define ELE_N  15
#define KSL    (ELE_N - 1)                          // 14 ele pair-slots
#define PLANE_SLOTS (AZI_N * KSL)                   // 420 slots per (b,r) plane
#define PLANE_OUTS  (AZI_N * ELE_N)                 // 450 out bins per plane
#define NPLANE (NB * RAD_N)                         // 80 planes
#define NSLOT  (NPLANE * PLANE_SLOTS)               // 33600 float4 2x2-slots
#define NOUT   (NPLANE * PLANE_OUTS)                // 36000 output bins

// 2x2 pair-slot histogram: slot[b][r][a][k] (a circular, k=0..13) holds
// contributions to bins (a,k),(a,k+1),(a+1%30,k),(a+1%30,k+1) in (.x,.y,.z,.w).
// INVARIANT: all-zero at entry of kernel_launch. Zero-initialized at module
// load; fold_reset_kernel restores zeros after reading, so every graph replay
// sees a clean table.
__device__ float4 g_slots[NSLOT];

__device__ __forceinline__ void red_add4(float4* a, float x, float y, float z, float w) {
    asm volatile("red.global.add.v4.f32 [%0], {%1, %2, %3, %4};"
                 :: "l"(a), "f"(x), "f"(y), "f"(z), "f"(w) : "memory");
}

__global__ void __launch_bounds__(256) vox_kernel(const float* __restrict__ pts) {
    int idx = blockIdx.x * blockDim.x + threadIdx.x;   // exact multiple, no guard
    float x = __ldg(pts + 3 * idx);
    float y = __ldg(pts + 3 * idx + 1);
    float z = __ldg(pts + 3 * idx + 2);

    float r = sqrtf(x * x + y * y + z * z);
    if (r > 2.0f) return;   // reference culls r > DES_R (all weights zero)

    int b = idx >> 16;      // NP = 65536

    float azi = atan2f(y, x);
    if (azi < 0.f) azi += 6.28318530717958647692f;
    float ce  = fminf(fmaxf(z / fmaxf(r, 1e-12f), -1.f), 1.f);
    float ele = acosf(ce);

    // radial pair: tr=0.4, closed form of ref's half-bin boundary clamps
    float vr = r * 2.5f - 0.5f;
    int jr; float wr0, wr1;
    if (vr < 0.f)        { jr = 0; wr0 = 1.f; wr1 = 0.f; }
    else if (vr >= 4.f)  { jr = 3; wr0 = 0.f; wr1 = 5.f - vr; }
    else { jr = (int)vr; float f = vr - (float)jr; wr0 = 1.f - f; wr1 = f; }

    // azimuth pair: circular; slot sa covers bins (sa, sa+1 mod 30)
    float va = azi * (float)(AZI_N / 6.283185307179586) - 0.5f;
    float fj = floorf(va);
    int   j  = (int)fj;                 // in [-1, 29]
    float fa = va - fj;
    int sa = (j < 0) ? (AZI_N - 1) : j;
    float wa0 = 1.f - fa, wa1 = fa;

    // elevation pair: te = pi/15, both-end half-bin clamps
    float ve = ele * (float)(ELE_N / 3.141592653589793) - 0.5f;
    int ke; float we0, we1;
    if (ve < 0.f)         { ke = 0;  we0 = 1.f; we1 = 0.f; }
    else if (ve >= 14.f)  { ke = 13; we0 = 0.f; we1 = 1.f; }
    else { ke = (int)ve; float f = ve - (float)ke; we0 = 1.f - f; we1 = f; }

    float p00 = wa0 * we0, p01 = wa0 * we1;
    float p10 = wa1 * we0, p11 = wa1 * we1;

    int s0 = ((b * RAD_N + jr) * AZI_N + sa) * KSL + ke;
    if (wr0 != 0.f)
        red_add4(&g_slots[s0], wr0 * p00, wr0 * p01, wr0 * p10, wr0 * p11);
    if (wr1 != 0.f)
        red_add4(&g_slots[s0 + PLANE_SLOTS], wr1 * p00, wr1 * p01, wr1 * p10, wr1 * p11);
}

// One block per (b,r) plane. Stages the plane's 420 slots in smem
// (L1-bypassed loads: red.global updates L2 only), immediately writes zeros
// back (restoring the invariant for the next replay), then folds 450 output
// bins from smem. All reads of a slot happen inside its owning block, so the
// read-then-zero is race-free.
__global__ void __launch_bounds__(512) fold_reset_kernel(float* __restrict__ out) {
    __shared__ float4 s[PLANE_SLOTS];
    int plane = blockIdx.x;              // rb = b*5 + r
    int tid = threadIdx.x;

    float4* gp = g_slots + plane * PLANE_SLOTS;
    if (tid < PLANE_SLOTS) {
        float4 v = __ldcg(&gp[tid]);
        s[tid] = v;
        __stcg(&gp[tid], make_float4(0.f, 0.f, 0.f, 0.f));
    }
    __syncthreads();

    if (tid < PLANE_OUTS) {
        int e   = tid % ELE_N;
        int a   = tid / ELE_N;
        int am1 = (a == 0) ? (AZI_N - 1) : (a - 1);

        float v = 0.f;
        if (e < KSL) {
            v += s[a   * KSL + e].x;
            v += s[am1 * KSL + e].z;
        }
        if (e > 0) {
            v += s[a   * KSL + e - 1].y;
            v += s[am1 * KSL + e - 1].w;
        }
        out[plane * PLANE_OUTS + tid] = v;
    }
}

extern "C" void kernel_launch(void* const* d_in, const int* in_sizes, int n_in,
                              void* d_out, int out_size) {
    const float* pts = (const float*)d_in[0];
    float* out = (float*)d_out;

    vox_kernel<<<(NB * NP) / 256, 256>>>(pts);
    fold_reset_kernel<<<NPLANE, 512>>>(out);
}